// round 13
// baseline (speedup 1.0000x reference)
#include <cuda_runtime.h>
#include <cuda_bf16.h>
#include <cuda_fp16.h>
#include <stdint.h>
#include <math.h>

// Problem constants
#define B_  2
#define S_  2048
#define D_  1024
#define H_  16
#define DH_ 64
#define M_ROWS (B_ * S_)

// 0.125 * log2(e)
#define QSCALE 0.18033688011112042f
// static softmax max bound (exp2 domain)
#define SMAX 8.0f

// ---------------------------------------------------------------------------
// Device-global scratch (allocation-free). Referenced ONLY from device code.
// ---------------------------------------------------------------------------
__device__ __align__(16) float g_q[B_ * H_ * S_ * DH_];
__device__ __align__(16) float g_k[B_ * H_ * S_ * DH_];

__device__ __align__(16) __nv_bfloat16 g_qh[B_ * H_ * S_ * DH_];
__device__ __align__(16) __nv_bfloat16 g_ql[B_ * H_ * S_ * DH_];
__device__ __align__(16) __nv_bfloat16 g_kh[B_ * H_ * S_ * DH_];
__device__ __align__(16) __nv_bfloat16 g_kl[B_ * H_ * S_ * DH_];
__device__ __align__(16) __half        g_vh[B_ * H_ * S_ * DH_];
__device__ __align__(16) __half        g_vl[B_ * H_ * S_ * DH_];

__device__ __align__(16) __nv_bfloat16 g_xhi[M_ROWS * D_];
__device__ __align__(16) __nv_bfloat16 g_xlo[M_ROWS * D_];
__device__ __align__(16) __nv_bfloat16 g_wqhi[D_ * 3 * D_];
__device__ __align__(16) __nv_bfloat16 g_wqlo[D_ * 3 * D_];
__device__ __align__(16) __nv_bfloat16 g_wohi[D_ * D_];
__device__ __align__(16) __nv_bfloat16 g_wolo[D_ * D_];
__device__ __align__(16) __nv_bfloat16 g_zhi[M_ROWS * D_];
__device__ __align__(16) __nv_bfloat16 g_zlo[M_ROWS * D_];

// ---------------------------------------------------------------------------
// PTX helpers (render-safe operand lists)
// ---------------------------------------------------------------------------
__device__ __forceinline__ unsigned int smem_u32(const void* p) {
    unsigned int addr;
    asm("{ .reg .u64 tmp; cvta.to.shared.u64 tmp, %1; cvt.u32.u64 %0, tmp; }"
        : "=r"(addr) : "l"(p));
    return addr;
}

#define LDSM_X4(R0, R1, R2, R3, ADDR)                                         \
    asm volatile(                                                             \
        "ldmatrix.sync.aligned.m8n8.x4.shared.b16 { %0, %1, %2, %3 }, [ %4 ];"\
        : "=r"(R0), "=r"(R1), "=r"(R2), "=r"(R3)                              \
        : "r"(ADDR))

#define LDSM_X2(R0, R1, ADDR)                                                 \
    asm volatile(                                                             \
        "ldmatrix.sync.aligned.m8n8.x2.shared.b16 { %0, %1 }, [ %2 ];"        \
        : "=r"(R0), "=r"(R1)                                                  \
        : "r"(ADDR))

#define LDSM_X2T(R0, R1, ADDR)                                                \
    asm volatile(                                                             \
        "ldmatrix.sync.aligned.m8n8.x2.trans.shared.b16 { %0, %1 }, [ %2 ];"  \
        : "=r"(R0), "=r"(R1)                                                  \
        : "r"(ADDR))

#define MMA_BF16(C0, C1, C2, C3, A0, A1, A2, A3, B0, B1)                      \
    asm volatile(                                                             \
        "mma.sync.aligned.m16n8k16.row.col.f32.bf16.bf16.f32 "                \
        "{ %0, %1, %2, %3 }, { %4, %5, %6, %7 }, { %8, %9 }, "                \
        "{ %0, %1, %2, %3 };"                                                 \
        : "+f"(C0), "+f"(C1), "+f"(C2), "+f"(C3)                              \
        : "r"(A0), "r"(A1), "r"(A2), "r"(A3), "r"(B0), "r"(B1))

#define MMA_F16(C0, C1, C2, C3, A0, A1, A2, A3, B0, B1)                       \
    asm volatile(                                                             \
        "mma.sync.aligned.m16n8k16.row.col.f32.f16.f16.f32 "                  \
        "{ %0, %1, %2, %3 }, { %4, %5, %6, %7 }, { %8, %9 }, "                \
        "{ %0, %1, %2, %3 };"                                                 \
        : "+f"(C0), "+f"(C1), "+f"(C2), "+f"(C3)                              \
        : "r"(A0), "r"(A1), "r"(A2), "r"(A3), "r"(B0), "r"(B1))

#define EX2F16X2(R, S0, S1)                                                   \
    do {                                                                      \
        unsigned int _t;                                                      \
        asm("cvt.rn.f16x2.f32 %0, %1, %2;" : "=r"(_t) : "f"(S1), "f"(S0));    \
        asm("ex2.approx.f16x2 %0, %1;" : "=r"(R) : "r"(_t));                  \
    } while (0)

#define CP_A16(DST, SRC)                                                      \
    asm volatile("cp.async.ca.shared.global [ %0 ], [ %1 ], 16;"              \
                 :: "r"(DST), "l"(SRC))
#define CP_COMMIT() asm volatile("cp.async.commit_group;" ::: "memory")
#define CP_WAIT0()  asm volatile("cp.async.wait_group 0;" ::: "memory")
#define CP_WAIT1()  asm volatile("cp.async.wait_group 1;" ::: "memory")

// ---------------------------------------------------------------------------
// Split fp32 -> (bf16 hi, bf16 lo). WHICH: 0 = x, 1 = W_qkv, 2 = W_o.
// ---------------------------------------------------------------------------
template <int WHICH>
__global__ void split_kernel(const float* src, int n) {
    int i = blockIdx.x * blockDim.x + threadIdx.x;
    if (i >= n) return;
    float v = src[i];
    __nv_bfloat16 hv = __float2bfloat16(v);
    __nv_bfloat16 lv = __float2bfloat16(v - __bfloat162float(hv));
    if (WHICH == 0) { g_xhi[i] = hv; g_xlo[i] = lv; }
    if (WHICH == 1) { g_wqhi[i] = hv; g_wqlo[i] = lv; }
    if (WHICH == 2) { g_wohi[i] = hv; g_wolo[i] = lv; }
}

// ---------------------------------------------------------------------------
// GEMM stage constants (3-stage pipeline)
// ---------------------------------------------------------------------------
#define GA_ELEMS (128 * 40)
#define GB_ELEMS (32 * 136)
#define GSTAGE_ELEMS (2 * GA_ELEMS + 2 * GB_ELEMS)   // 18944 elems
#define GEMM_SMEM_BYTES (3 * GSTAGE_ELEMS * 2)       // 113664

__device__ __forceinline__ void gemm_stage_load(
    __nv_bfloat16* Ah, __nv_bfloat16* Al,
    __nv_bfloat16* Bh, __nv_bfloat16* Bl,
    const __nv_bfloat16* Ahi, const __nv_bfloat16* Alo,
    const __nv_bfloat16* Bhi, const __nv_bfloat16* Blo,
    int tid, int m0, int n0, int k0, int N) {
#pragma unroll
    for (int i = 0; i < 2; i++) {
        int idx = tid + i * 256;
        int rr = idx >> 2;
        int cc = (idx & 3) * 8;
        CP_A16(smem_u32(&Ah[rr * 40 + cc]), &Ahi[(size_t)(m0 + rr) * 1024 + k0 + cc]);
        CP_A16(smem_u32(&Al[rr * 40 + cc]), &Alo[(size_t)(m0 + rr) * 1024 + k0 + cc]);
    }
#pragma unroll
    for (int i = 0; i < 2; i++) {
        int idx = tid + i * 256;
        int rr = idx >> 4;
        int cc = (idx & 15) * 8;
        CP_A16(smem_u32(&Bh[rr * 136 + cc]), &Bhi[(size_t)(k0 + rr) * N + n0 + cc]);
        CP_A16(smem_u32(&Bl[rr * 136 + cc]), &Blo[(size_t)(k0 + rr) * N + n0 + cc]);
    }
}

// ---------------------------------------------------------------------------
// Split-bf16 tensor-core GEMM, cp.async 3-stage pipelined, 1 sync/iter.
// ---------------------------------------------------------------------------
template <int N, int MODE>
__global__ __launch_bounds__(256) void mma_gemm(float* __restrict__ C) {
    extern __shared__ __align__(16) char dynsmem[];
    __nv_bfloat16* sbase = (__nv_bfloat16*)dynsmem;

    const __nv_bfloat16* Ahi;
    const __nv_bfloat16* Alo;
    const __nv_bfloat16* Bhi;
    const __nv_bfloat16* Blo;
    if (MODE == 1) {
        Ahi = &g_xhi[0];
        Alo = &g_xlo[0];
        Bhi = &g_wqhi[0];
        Blo = &g_wqlo[0];
    } else {
        Ahi = &g_zhi[0];
        Alo = &g_zlo[0];
        Bhi = &g_wohi[0];
        Blo = &g_wolo[0];
    }

    const int tid = threadIdx.x;
    const int lane = tid & 31;
    const int wid = tid >> 5;
    const int warp_m = wid >> 2;
    const int warp_n = wid & 3;
    const int m0 = blockIdx.y * 128;
    const int n0 = blockIdx.x * 128;

    float acc[4][4][4];
#pragma unroll
    for (int i = 0; i < 4; i++) {
#pragma unroll
        for (int j = 0; j < 4; j++) {
#pragma unroll
            for (int e = 0; e < 4; e++) {
                acc[i][j][e] = 0.f;
            }
        }
    }

    const int a_r = lane & 15;
    const int a_c = ((lane & 16) != 0) ? 8 : 0;
    const int b_r = lane & 15;
    const int NK = 1024 / 32;

    // Prologue: stages 0, 1
#pragma unroll
    for (int p = 0; p < 2; p++) {
        __nv_bfloat16* Ah = sbase + p * GSTAGE_ELEMS;
        __nv_bfloat16* Al = Ah + GA_ELEMS;
        __nv_bfloat16* Bh = Al + GA_ELEMS;
        __nv_bfloat16* Bl = Bh + GB_ELEMS;
        gemm_stage_load(Ah, Al, Bh, Bl, Ahi, Alo, Bhi, Blo, tid, m0, n0, p * 32, N);
        CP_COMMIT();
    }

    for (int kt = 0; kt < NK; kt++) {
        if (kt + 1 < NK) {
            CP_WAIT1();
        } else {
            CP_WAIT0();
        }
        __syncthreads();

        if (kt + 2 < NK) {
            int st = (kt + 2) % 3;
            __nv_bfloat16* Ah2 = sbase + st * GSTAGE_ELEMS;
            __nv_bfloat16* Al2 = Ah2 + GA_ELEMS;
            __nv_bfloat16* Bh2 = Al2 + GA_ELEMS;
            __nv_bfloat16* Bl2 = Bh2 + GB_ELEMS;
            gemm_stage_load(Ah2, Al2, Bh2, Bl2, Ahi, Alo, Bhi, Blo,
                            tid, m0, n0, (kt + 2) * 32, N);
            CP_COMMIT();
        }

        __nv_bfloat16* Ah = sbase + (kt % 3) * GSTAGE_ELEMS;
        __nv_bfloat16* Al = Ah + GA_ELEMS;
        __nv_bfloat16* Bh = Al + GA_ELEMS;
        __nv_bfloat16* Bl = Bh + GB_ELEMS;

#pragma unroll
        for (int ks = 0; ks < 2; ks++) {
            unsigned int bh0[4];
            unsigned int bh1[4];
            unsigned int bl0[4];
            unsigned int bl1[4];
#pragma unroll
            for (int nf = 0; nf < 4; nf++) {
                LDSM_X2T(bh0[nf], bh1[nf],
                         smem_u32(&Bh[(ks * 16 + b_r) * 136 + warp_n * 32 + nf * 8]));
                LDSM_X2T(bl0[nf], bl1[nf],
                         smem_u32(&Bl[(ks * 16 + b_r) * 136 + warp_n * 32 + nf * 8]));
            }
#pragma unroll
            for (int mf = 0; mf < 4; mf++) {
                unsigned int ah0;
                unsigned int ah1;
                unsigned int ah2;
                unsigned int ah3;
                unsigned int al0;
                unsigned int al1;
                unsigned int al2;
                unsigned int al3;
                LDSM_X4(ah0, ah1, ah2, ah3,
                        smem_u32(&Ah[(warp_m * 64 + mf * 16 + a_r) * 40 + ks * 16 + a_c]));
                LDSM_X4(al0, al1, al2, al3,
                        smem_u32(&Al[(warp_m * 64 + mf * 16 + a_r) * 40 + ks * 16 + a_c]));
#pragma unroll
                for (int nf = 0; nf < 4; nf++) {
                    MMA_BF16(acc[mf][nf][0], acc[mf][nf][1], acc[mf][nf][2], acc[mf][nf][3],
                             ah0, ah1, ah2, ah3, bh0[nf], bh1[nf]);
                    MMA_BF16(acc[mf][nf][0], acc[mf][nf][1], acc[mf][nf][2], acc[mf][nf][3],
                             ah0, ah1, ah2, ah3, bl0[nf], bl1[nf]);
                    MMA_BF16(acc[mf][nf][0], acc[mf][nf][1], acc[mf][nf][2], acc[mf][nf][3],
                             al0, al1, al2, al3, bh0[nf], bh1[nf]);
                }
            }
        }
    }

    const int gg = lane >> 2;
    const int t2 = (lane & 3) * 2;
#pragma unroll
    for (int mf = 0; mf < 4; mf++) {
#pragma unroll
        for (int nf = 0; nf < 4; nf++) {
#pragma unroll
            for (int e = 0; e < 4; e++) {
                const int row = warp_m * 64 + mf * 16 + gg + ((e >= 2) ? 8 : 0);
                const int col = warp_n * 32 + nf * 8 + t2 + (e & 1);
                const int m = m0 + row;
                const int ecol = n0 + col;
                const float v = acc[mf][nf][e];
                if (MODE == 1) {
                    const int bb = m >> 11;
                    const int ss = m & 2047;
                    const int c3 = ecol >> 10;
                    const int rem = ecol & 1023;
                    const int hh = rem >> 6;
                    const int dd = rem & 63;
                    const size_t di = (size_t)(((bb << 4) + hh) * S_ + ss) * DH_ + dd;
                    if (c3 == 0) {
                        g_q[di] = v;
                    } else if (c3 == 1) {
                        g_k[di] = v;
                    } else {
                        __half hv = __float2half_rn(v);
                        g_vh[di] = hv;
                        g_vl[di] = __float2half_rn(v - __half2float(hv));
                    }
                } else {
                    C[(size_t)m * N + ecol] = v;
                }
            }
        }
    }
}

// ---------------------------------------------------------------------------
// RoPE: reads fp32 g_q/g_k, rotates, writes split-bf16 (q scaled by QSCALE).
// ---------------------------------------------------------------------------
__global__ void rope2_kernel() {
    const int total = B_ * H_ * S_ * 32;
    int idx = blockIdx.x * blockDim.x + threadIdx.x;
    bool isq = true;
    if (idx >= total) {
        isq = false;
        idx -= total;
    }
    const float* src;
    if (isq) {
        src = &g_q[0];
    } else {
        src = &g_k[0];
    }

    const int i = idx & 31;
    const int s = (idx >> 5) & (S_ - 1);
    const int base = (idx >> 5) << 6;

    const float invf = (float)exp(-log(10000.0) * (double)i / 32.0);
    const float ang = (float)s * invf;
    const float cv = cosf(ang);
    const float sv = sinf(ang);

    const float u1 = src[base + i];
    const float u2 = src[base + 32 + i];
    float v1 = u1 * cv - u2 * sv;
    float v2 = u2 * cv + u1 * sv;
    if (isq) {
        v1 *= QSCALE;
        v2 *= QSCALE;
        __nv_bfloat16 h1 = __float2bfloat16(v1);
        __nv_bfloat16 h2 = __float2bfloat16(v2);
        g_qh[base + i] = h1;
        g_ql[base + i] = __float2bfloat16(v1 - __bfloat162float(h1));
        g_qh[base + 32 + i] = h2;
        g_ql[base + 32 + i] = __float2bfloat16(v2 - __bfloat162float(h2));
    } else {
        __nv_bfloat16 h1 = __float2bfloat16(v1);
        __nv_bfloat16 h2 = __float2bfloat16(v2);
        g_kh[base + i] = h1;
        g_kl[base + i] = __float2bfloat16(v1 - __bfloat162float(h1));
        g_kh[base + 32 + i] = h2;
        g_kl[base + 32 + i] = __float2bfloat16(v2 - __bfloat162float(h2));
    }
}

// ---------------------------------------------------------------------------
// Attention stage constants (3-stage pipeline)
// ---------------------------------------------------------------------------
#define ATT_TILE 4608                        // 64*72 elems
#define ATT_STAGE_BYTES (4 * ATT_TILE * 2)   // Kh,Kl,Vh,Vl = 36864 B
#define ATTN_SMEM_BYTES (3 * ATT_STAGE_BYTES)  // 110592

__device__ __forceinline__ void attn_stage_load(char* sb, size_t base, int kt, int tid) {
    __nv_bfloat16* Kh = (__nv_bfloat16*)sb;
    __nv_bfloat16* Kl = Kh + ATT_TILE;
    __half* Vh = (__half*)(Kl + ATT_TILE);
    __half* Vl = Vh + ATT_TILE;
    for (int i = tid; i < 512; i += 128) {
        int rr = i >> 3;
        int cc = (i & 7) * 8;
        size_t gi = base + (size_t)(kt * 64 + rr) * 64 + cc;
        CP_A16(smem_u32(&Kh[rr * 72 + cc]), &g_kh[gi]);
        CP_A16(smem_u32(&Kl[rr * 72 + cc]), &g_kl[gi]);
        CP_A16(smem_u32(&Vh[rr * 72 + cc]), &g_vh[gi]);
        CP_A16(smem_u32(&Vl[rr * 72 + cc]), &g_vl[gi]);
    }
}

// ---------------------------------------------------------------------------
// Tensor-core causal flash attention, static-max softmax, 3-stage cp.async.
// Scores accumulate on top of init = -SMAX (exp2 domain), so P = exp2(s-SMAX)
// directly; no online max, no rescaling; l reduced once at the end.
// ---------------------------------------------------------------------------
__global__ __launch_bounds__(128) void attn_tc() {
    extern __shared__ __align__(16) char dynsmem[];

    const int tid = threadIdx.x;
    const int lane = tid & 31;
    const int wid = tid >> 5;
    const int qt = (int)gridDim.x - 1 - (int)blockIdx.x;
    const int bh = blockIdx.y;

    const size_t base = (size_t)bh * S_ * DH_;

    // stage Q into stage-0 area, move to registers
    {
        __nv_bfloat16* Kh0 = (__nv_bfloat16*)dynsmem;
        __nv_bfloat16* Kl0 = Kh0 + ATT_TILE;
        for (int i = tid; i < 512; i += 128) {
            int rr = i >> 3;
            int cc = (i & 7) * 8;
            *(uint4*)(&Kh0[rr * 72 + cc]) =
                *(const uint4*)(&g_qh[base + (size_t)(qt * 64 + rr) * 64 + cc]);
            *(uint4*)(&Kl0[rr * 72 + cc]) =
                *(const uint4*)(&g_ql[base + (size_t)(qt * 64 + rr) * 64 + cc]);
        }
    }
    __syncthreads();

    const int a_r = lane & 15;
    const int a_c = ((lane & 16) != 0) ? 8 : 0;
    unsigned int qh[4][4];
    unsigned int ql[4][4];
    {
        __nv_bfloat16* Kh0 = (__nv_bfloat16*)dynsmem;
        __nv_bfloat16* Kl0 = Kh0 + ATT_TILE;
#pragma unroll
        for (int kc = 0; kc < 4; kc++) {
            LDSM_X4(qh[kc][0], qh[kc][1], qh[kc][2], qh[kc][3],
                    smem_u32(&Kh0[(wid * 16 + a_r) * 72 + kc * 16 + a_c]));
            LDSM_X4(ql[kc][0], ql[kc][1], ql[kc][2], ql[kc][3],
                    smem_u32(&Kl0[(wid * 16 + a_r) * 72 + kc * 16 + a_c]));
        }
    }
    __syncthreads();   // Q consumed before stage-0 overwrite

    float o[8][4];
#pragma unroll
    for (int nf = 0; nf < 8; nf++) {
#pragma unroll
        for (int e = 0; e < 4; e++) {
            o[nf][e] = 0.f;
        }
    }
    float l0r = 0.f;
    float l1r = 0.f;

    const int b_row = lane & 7;
    const int b_sel = ((lane >> 3) & 1) * 8;

    // prologue: stages 0 (kt=0) and 1 (kt=1 if present)
    attn_stage_load(dynsmem, base, 0, tid);
    CP_COMMIT();
    if (qt >= 1) {
        attn_stage_load(dynsmem + ATT_STAGE_BYTES, base, 1, tid);
        CP_COMMIT();
    }

    for (int kt = 0; kt <= qt; kt++) {
        if (kt + 1 <= qt) {
            CP_WAIT1();
        } else {
            CP_WAIT0();
        }
        __syncthreads();

        if (kt + 2 <= qt) {
            attn_stage_load(dynsmem + ((kt + 2) % 3) * ATT_STAGE_BYTES, base, kt + 2, tid);
            CP_COMMIT();
        }

        char* sb = dynsmem + (kt % 3) * ATT_STAGE_BYTES;
        __nv_bfloat16* Kh = (__nv_bfloat16*)sb;
        __nv_bfloat16* Kl = Kh + ATT_TILE;
        __half* Vh = (__half*)(Kl + ATT_TILE);
        __half* Vl = Vh + ATT_TILE;

        // S - SMAX = Q K^T (accumulator initialized at -SMAX)
        float sc[8][4];
#pragma unroll
        for (int nf = 0; nf < 8; nf++) {
#pragma unroll
            for (int e = 0; e < 4; e++) {
                sc[nf][e] = -SMAX;
            }
        }
#pragma unroll
        for (int nf = 0; nf < 8; nf++) {
#pragma unroll
            for (int kc = 0; kc < 4; kc++) {
                unsigned int kbh0;
                unsigned int kbh1;
                unsigned int kbl0;
                unsigned int kbl1;
                LDSM_X2(kbh0, kbh1, smem_u32(&Kh[(nf * 8 + b_row) * 72 + kc * 16 + b_sel]));
                LDSM_X2(kbl0, kbl1, smem_u32(&Kl[(nf * 8 + b_row) * 72 + kc * 16 + b_sel]));
                MMA_BF16(sc[nf][0], sc[nf][1], sc[nf][2], sc[nf][3],
                         qh[kc][0], qh[kc][1], qh[kc][2], qh[kc][3], kbh0, kbh1);
                MMA_BF16(sc[nf][0], sc[nf][1], sc[nf][2], sc[nf][3],
                         qh[kc][0], qh[kc][1], qh[kc][2], qh[kc][3], kbl0, kbl1);
                MMA_BF16(sc[nf][0], sc[nf][1], sc[nf][2], sc[nf][3],
                         ql[kc][0], ql[kc][1], ql[kc][2], ql[kc][3], kbh0, kbh1);
            }
        }

        if (kt == qt) {
            const int lr0 = wid * 16 + (lane >> 2);
#pragma unroll
            for (int nf = 0; nf < 8; nf++) {
#pragma unroll
                for (int e = 0; e < 4; e++) {
                    const int lr = lr0 + ((e >= 2) ? 8 : 0);
                    const int lc = nf * 8 + (lane & 3) * 2 + (e & 1);
                    if (lc > lr) {
                        sc[nf][e] = -1e30f;
                    }
                }
            }
        }

        // P = exp2(S - SMAX) packed f16x2; accumulate row sums (no shuffles)
        unsigned int pf[4][4];
        float ts0 = 0.f;
        float ts1 = 0.f;
#pragma unroll
        for (int kc = 0; kc < 4; kc++) {
            EX2F16X2(pf[kc][0], sc[2 * kc][0], sc[2 * kc][1]);
            EX2F16X2(pf[kc][1], sc[2 * kc][2], sc[2 * kc][3]);
            EX2F16X2(pf[kc][2], sc[2 * kc + 1][0], sc[2 * kc + 1][1]);
            EX2F16X2(pf[kc][3], sc[2 * kc + 1][2], sc[2 * kc + 1][3]);
#pragma unroll
            for (int e = 0; e < 4; e++) {
                unsigned int u = pf[kc][e];
                __half2 hv = *(__half2*)(&u);
                float2 fv = __half22float2(hv);
                if ((e & 1) == 0) {
                    ts0 += fv.x + fv.y;
                } else {
                    ts1 += fv.x + fv.y;
                }
            }
        }
        l0r += ts0;
        l1r += ts1;

        // O += P V (f16, 2-pass)
#pragma unroll
        for (int nf = 0; nf < 8; nf++) {
#pragma unroll
            for (int kc = 0; kc < 4; kc++) {
                unsigned int vb0;
                unsigned int vb1;
                unsigned int wb0;
                unsigned int wb1;
                LDSM_X2T(vb0, vb1, smem_u32(&Vh[(kc * 16 + a_r) * 72 + nf * 8]));
                LDSM_X2T(wb0, wb1, smem_u32(&Vl[(kc * 16 + a_r) * 72 + nf * 8]));
                MMA_F16(o[nf][0], o[nf][1], o[nf][2], o[nf][3],
                        pf[kc][0], pf[kc][1], pf[kc][2], pf[kc][3], vb0, vb1);
                MMA_F16(o[nf][0], o[nf][1], o[nf][2], o[nf][3],
                        pf[kc][0], pf[kc][1], pf[kc][2], pf[kc][3], wb0, wb1);
            }
        }
    }

    // one quad-reduction at the end
    l0r += __shfl_xor_sync(0xffffffffu, l0r, 1);
    l0r += __shfl_xor_sync(0xffffffffu, l0r, 2);
    l1r += __shfl_xor_sync(0xffffffffu, l1r, 1);
    l1r += __shfl_xor_sync(0xffffffffu, l1r, 2);

    const float inv0 = 1.f / l0r;
    const float inv1 = 1.f / l1r;
    const int bb = bh >> 4;
    const int hh = bh & 15;
    const int row0 = qt * 64 + wid * 16 + (lane >> 2);
    const int col0 = (lane & 3) * 2;
#pragma unroll
    for (int nf = 0; nf < 8; nf++) {
        const float z00 = o[nf][0] * inv0;
        const float z01 = o[nf][1] * inv0;
        const float z10 = o[nf][2] * inv1;
        const float z11 = o[nf][3] * inv1;
        const size_t i0 = (size_t)(bb * S_ + row0) * D_ + hh * 64 + nf * 8 + col0;
        const size_t i1 = (size_t)(bb * S_ + row0 + 8) * D_ + hh * 64 + nf * 8 + col0;
        __nv_bfloat16 h00 = __float2bfloat16(z00);
        __nv_bfloat16 h01 = __float2bfloat16(z01);
        __nv_bfloat16 h10 = __float2bfloat16(z10);
        __nv_bfloat16 h11 = __float2bfloat16(z11);
        g_zhi[i0] = h00;
        g_zhi[i0 + 1] = h01;
        g_zhi[i1] = h10;
        g_zhi[i1 + 1] = h11;
        g_zlo[i0] = __float2bfloat16(z00 - __bfloat162float(h00));
        g_zlo[i0 + 1] = __float2bfloat16(z01 - __bfloat162float(h01));
        g_zlo[i1] = __float2bfloat16(z10 - __bfloat162float(h10));
        g_zlo[i1 + 1] = __float2bfloat16(z11 - __bfloat162float(h11));
    }
}

// ---------------------------------------------------------------------------
extern "C" void kernel_launch(void* const* d_in, const int* in_sizes, int n_in,
                              void* d_out, int out_size) {
    const float* x = 0;
    const float* W_qkv = 0;
    const float* W_o = 0;

    bool elem_mode = false;
    bool byte_mode = false;
    for (int i = 0; i < n_in; i++) {
        if (in_sizes[i] == 3145728)  elem_mode = true;
        if (in_sizes[i] == 12582912) byte_mode = true;
    }
    if (elem_mode) {
        for (int i = 0; i < n_in; i++) {
            if (in_sizes[i] == 4194304)      x     = (const float*)d_in[i];
            else if (in_sizes[i] == 3145728) W_qkv = (const float*)d_in[i];
            else if (in_sizes[i] == 1048576) W_o   = (const float*)d_in[i];
        }
    } else if (byte_mode) {
        for (int i = 0; i < n_in; i++) {
            if (in_sizes[i] == 16777216)      x     = (const float*)d_in[i];
            else if (in_sizes[i] == 12582912) W_qkv = (const float*)d_in[i];
            else if (in_sizes[i] == 4194304)  W_o   = (const float*)d_in[i];
        }
    }
    if (x == 0 || W_qkv == 0 || W_o == 0) {
        x     = (const float*)d_in[0];
        W_qkv = (const float*)d_in[1];
        W_o   = (const float*)d_in[2];
    }
    float* out = (float*)d_out;

    cudaFuncSetAttribute(mma_gemm<3072, 1>,
                         cudaFuncAttributeMaxDynamicSharedMemorySize, GEMM_SMEM_BYTES);
    cudaFuncSetAttribute(mma_gemm<1024, 0>,
                         cudaFuncAttributeMaxDynamicSharedMemorySize, GEMM_SMEM_BYTES);
    cudaFuncSetAttribute(attn_tc,
                         cudaFuncAttributeMaxDynamicSharedMemorySize, ATTN_SMEM_BYTES);

    // 0) split inputs to bf16 hi/lo
    split_kernel<0><<<(M_ROWS * D_ + 255) / 256, 256>>>(x, M_ROWS * D_);
    split_kernel<1><<<(D_ * 3 * D_ + 255) / 256, 256>>>(W_qkv, D_ * 3 * D_);
    split_kernel<2><<<(D_ * D_ + 255) / 256, 256>>>(W_o, D_ * D_);

    // 1) QKV projection (3-stage pipelined tensor cores)
    mma_gemm<3072, 1><<<dim3(3072 / 128, M_ROWS / 128), 256, GEMM_SMEM_BYTES>>>(0);

    // 2) RoPE + split/scale q,k
    rope2_kernel<<<(2 * B_ * H_ * S_ * 32) / 256, 256>>>();

    // 3) Static-max tensor-core causal flash attention
    attn_tc<<<dim3(S_ / 64, B_ * H_), 128, ATTN_SMEM_BYTES>>>();

    // 4) O-projection (3-stage pipelined tensor cores)
    mma_gemm<1024, 0><<<dim3(1024 / 128, M_ROWS / 128), 256, GEMM_SMEM_BYTES>>>(out);
}

// round 16
// speedup vs baseline: 1.5862x; 1.5862x over previous
#include <cuda_runtime.h>
#include <cuda_bf16.h>
#include <cuda_fp16.h>
#include <stdint.h>
#include <math.h>

// Problem constants
#define B_  2
#define S_  2048
#define D_  1024
#define H_  16
#define DH_ 64
#define M_ROWS (B_ * S_)

// 0.125 * log2(e)
#define QSCALE 0.18033688011112042f

// ---------------------------------------------------------------------------
// Device-global scratch (allocation-free). Referenced ONLY from device code.
// ---------------------------------------------------------------------------
__device__ __align__(16) float g_q[B_ * H_ * S_ * DH_];
__device__ __align__(16) float g_k[B_ * H_ * S_ * DH_];

__device__ __align__(16) __nv_bfloat16 g_qh[B_ * H_ * S_ * DH_];
__device__ __align__(16) __nv_bfloat16 g_ql[B_ * H_ * S_ * DH_];
__device__ __align__(16) __nv_bfloat16 g_kh[B_ * H_ * S_ * DH_];
__device__ __align__(16) __nv_bfloat16 g_kl[B_ * H_ * S_ * DH_];
__device__ __align__(16) __half        g_vh[B_ * H_ * S_ * DH_];
__device__ __align__(16) __half        g_vl[B_ * H_ * S_ * DH_];

__device__ __align__(16) __nv_bfloat16 g_xhi[M_ROWS * D_];
__device__ __align__(16) __nv_bfloat16 g_xlo[M_ROWS * D_];
__device__ __align__(16) __nv_bfloat16 g_wqhi[D_ * 3 * D_];
__device__ __align__(16) __nv_bfloat16 g_wqlo[D_ * 3 * D_];
__device__ __align__(16) __nv_bfloat16 g_wohi[D_ * D_];
__device__ __align__(16) __nv_bfloat16 g_wolo[D_ * D_];
__device__ __align__(16) __nv_bfloat16 g_zhi[M_ROWS * D_];
__device__ __align__(16) __nv_bfloat16 g_zlo[M_ROWS * D_];

// ---------------------------------------------------------------------------
// PTX helpers (render-safe operand lists)
// ---------------------------------------------------------------------------
__device__ __forceinline__ unsigned int smem_u32(const void* p) {
    unsigned int addr;
    asm("{ .reg .u64 tmp; cvta.to.shared.u64 tmp, %1; cvt.u32.u64 %0, tmp; }"
        : "=r"(addr) : "l"(p));
    return addr;
}

#define LDSM_X4(R0, R1, R2, R3, ADDR)                                         \
    asm volatile(                                                             \
        "ldmatrix.sync.aligned.m8n8.x4.shared.b16 { %0, %1, %2, %3 }, [ %4 ];"\
        : "=r"(R0), "=r"(R1), "=r"(R2), "=r"(R3)                              \
        : "r"(ADDR))

#define LDSM_X2(R0, R1, ADDR)                                                 \
    asm volatile(                                                             \
        "ldmatrix.sync.aligned.m8n8.x2.shared.b16 { %0, %1 }, [ %2 ];"        \
        : "=r"(R0), "=r"(R1)                                                  \
        : "r"(ADDR))

#define LDSM_X2T(R0, R1, ADDR)                                                \
    asm volatile(                                                             \
        "ldmatrix.sync.aligned.m8n8.x2.trans.shared.b16 { %0, %1 }, [ %2 ];"  \
        : "=r"(R0), "=r"(R1)                                                  \
        : "r"(ADDR))

#define MMA_BF16(C0, C1, C2, C3, A0, A1, A2, A3, B0, B1)                      \
    asm volatile(                                                             \
        "mma.sync.aligned.m16n8k16.row.col.f32.bf16.bf16.f32 "                \
        "{ %0, %1, %2, %3 }, { %4, %5, %6, %7 }, { %8, %9 }, "                \
        "{ %0, %1, %2, %3 };"                                                 \
        : "+f"(C0), "+f"(C1), "+f"(C2), "+f"(C3)                              \
        : "r"(A0), "r"(A1), "r"(A2), "r"(A3), "r"(B0), "r"(B1))

#define MMA_F16(C0, C1, C2, C3, A0, A1, A2, A3, B0, B1)                       \
    asm volatile(                                                             \
        "mma.sync.aligned.m16n8k16.row.col.f32.f16.f16.f32 "                  \
        "{ %0, %1, %2, %3 }, { %4, %5, %6, %7 }, { %8, %9 }, "                \
        "{ %0, %1, %2, %3 };"                                                 \
        : "+f"(C0), "+f"(C1), "+f"(C2), "+f"(C3)                              \
        : "r"(A0), "r"(A1), "r"(A2), "r"(A3), "r"(B0), "r"(B1))

#define EX2F16X2(R, S0, S1)                                                   \
    do {                                                                      \
        unsigned int _t;                                                      \
        asm("cvt.rn.f16x2.f32 %0, %1, %2;" : "=r"(_t) : "f"(S1), "f"(S0));    \
        asm("ex2.approx.f16x2 %0, %1;" : "=r"(R) : "r"(_t));                  \
    } while (0)

#define CP_A16(DST, SRC)                                                      \
    asm volatile("cp.async.ca.shared.global [ %0 ], [ %1 ], 16;"              \
                 :: "r"(DST), "l"(SRC))
#define CP_COMMIT() asm volatile("cp.async.commit_group;" ::: "memory")
#define CP_WAIT0()  asm volatile("cp.async.wait_group 0;" ::: "memory")
#define CP_WAIT1()  asm volatile("cp.async.wait_group 1;" ::: "memory")

// ---------------------------------------------------------------------------
// Split fp32 -> (bf16 hi, bf16 lo). WHICH: 0 = x, 1 = W_qkv, 2 = W_o.
// ---------------------------------------------------------------------------
template <int WHICH>
__global__ void split_kernel(const float* src, int n) {
    int i = blockIdx.x * blockDim.x + threadIdx.x;
    if (i >= n) return;
    float v = src[i];
    __nv_bfloat16 hv = __float2bfloat16(v);
    __nv_bfloat16 lv = __float2bfloat16(v - __bfloat162float(hv));
    if (WHICH == 0) { g_xhi[i] = hv; g_xlo[i] = lv; }
    if (WHICH == 1) { g_wqhi[i] = hv; g_wqlo[i] = lv; }
    if (WHICH == 2) { g_wohi[i] = hv; g_wolo[i] = lv; }
}

// ---------------------------------------------------------------------------
// GEMM stage constants (2-stage pipeline, validated round 10)
// ---------------------------------------------------------------------------
#define GA_ELEMS (128 * 40)
#define GB_ELEMS (32 * 136)
#define GSTAGE_ELEMS (2 * GA_ELEMS + 2 * GB_ELEMS)
#define GEMM_SMEM_BYTES (2 * GSTAGE_ELEMS * 2)      // 75776

__device__ __forceinline__ void gemm_stage_load(
    __nv_bfloat16* Ah, __nv_bfloat16* Al,
    __nv_bfloat16* Bh, __nv_bfloat16* Bl,
    const __nv_bfloat16* Ahi, const __nv_bfloat16* Alo,
    const __nv_bfloat16* Bhi, const __nv_bfloat16* Blo,
    int tid, int m0, int n0, int k0, int N) {
#pragma unroll
    for (int i = 0; i < 2; i++) {
        int idx = tid + i * 256;
        int rr = idx >> 2;
        int cc = (idx & 3) * 8;
        CP_A16(smem_u32(&Ah[rr * 40 + cc]), &Ahi[(size_t)(m0 + rr) * 1024 + k0 + cc]);
        CP_A16(smem_u32(&Al[rr * 40 + cc]), &Alo[(size_t)(m0 + rr) * 1024 + k0 + cc]);
    }
#pragma unroll
    for (int i = 0; i < 2; i++) {
        int idx = tid + i * 256;
        int rr = idx >> 4;
        int cc = (idx & 15) * 8;
        CP_A16(smem_u32(&Bh[rr * 136 + cc]), &Bhi[(size_t)(k0 + rr) * N + n0 + cc]);
        CP_A16(smem_u32(&Bl[rr * 136 + cc]), &Blo[(size_t)(k0 + rr) * N + n0 + cc]);
    }
}

// ---------------------------------------------------------------------------
// Split-bf16 tensor-core GEMM, cp.async 2-stage pipelined (round-10 form).
// ---------------------------------------------------------------------------
template <int N, int MODE>
__global__ __launch_bounds__(256) void mma_gemm(float* __restrict__ C) {
    extern __shared__ __align__(16) char dynsmem[];
    __nv_bfloat16* sbase = (__nv_bfloat16*)dynsmem;

    const __nv_bfloat16* Ahi;
    const __nv_bfloat16* Alo;
    const __nv_bfloat16* Bhi;
    const __nv_bfloat16* Blo;
    if (MODE == 1) {
        Ahi = &g_xhi[0];
        Alo = &g_xlo[0];
        Bhi = &g_wqhi[0];
        Blo = &g_wqlo[0];
    } else {
        Ahi = &g_zhi[0];
        Alo = &g_zlo[0];
        Bhi = &g_wohi[0];
        Blo = &g_wolo[0];
    }

    const int tid = threadIdx.x;
    const int lane = tid & 31;
    const int wid = tid >> 5;
    const int warp_m = wid >> 2;
    const int warp_n = wid & 3;
    const int m0 = blockIdx.y * 128;
    const int n0 = blockIdx.x * 128;

    float acc[4][4][4];
#pragma unroll
    for (int i = 0; i < 4; i++) {
#pragma unroll
        for (int j = 0; j < 4; j++) {
#pragma unroll
            for (int e = 0; e < 4; e++) {
                acc[i][j][e] = 0.f;
            }
        }
    }

    const int a_r = lane & 15;
    const int a_c = ((lane & 16) != 0) ? 8 : 0;
    const int b_r = lane & 15;
    const int NK = 1024 / 32;

    {
        __nv_bfloat16* Ah = sbase;
        __nv_bfloat16* Al = Ah + GA_ELEMS;
        __nv_bfloat16* Bh = Al + GA_ELEMS;
        __nv_bfloat16* Bl = Bh + GB_ELEMS;
        gemm_stage_load(Ah, Al, Bh, Bl, Ahi, Alo, Bhi, Blo, tid, m0, n0, 0, N);
        CP_COMMIT();
    }

    for (int kt = 0; kt < NK; kt++) {
        if (kt + 1 < NK) {
            __nv_bfloat16* Ah = sbase + ((kt + 1) & 1) * GSTAGE_ELEMS;
            __nv_bfloat16* Al = Ah + GA_ELEMS;
            __nv_bfloat16* Bh = Al + GA_ELEMS;
            __nv_bfloat16* Bl = Bh + GB_ELEMS;
            gemm_stage_load(Ah, Al, Bh, Bl, Ahi, Alo, Bhi, Blo,
                            tid, m0, n0, (kt + 1) * 32, N);
            CP_COMMIT();
            CP_WAIT1();
        } else {
            CP_WAIT0();
        }
        __syncthreads();

        __nv_bfloat16* Ah = sbase + (kt & 1) * GSTAGE_ELEMS;
        __nv_bfloat16* Al = Ah + GA_ELEMS;
        __nv_bfloat16* Bh = Al + GA_ELEMS;
        __nv_bfloat16* Bl = Bh + GB_ELEMS;

#pragma unroll
        for (int ks = 0; ks < 2; ks++) {
            unsigned int bh0[4];
            unsigned int bh1[4];
            unsigned int bl0[4];
            unsigned int bl1[4];
#pragma unroll
            for (int nf = 0; nf < 4; nf++) {
                LDSM_X2T(bh0[nf], bh1[nf],
                         smem_u32(&Bh[(ks * 16 + b_r) * 136 + warp_n * 32 + nf * 8]));
                LDSM_X2T(bl0[nf], bl1[nf],
                         smem_u32(&Bl[(ks * 16 + b_r) * 136 + warp_n * 32 + nf * 8]));
            }
#pragma unroll
            for (int mf = 0; mf < 4; mf++) {
                unsigned int ah0;
                unsigned int ah1;
                unsigned int ah2;
                unsigned int ah3;
                unsigned int al0;
                unsigned int al1;
                unsigned int al2;
                unsigned int al3;
                LDSM_X4(ah0, ah1, ah2, ah3,
                        smem_u32(&Ah[(warp_m * 64 + mf * 16 + a_r) * 40 + ks * 16 + a_c]));
                LDSM_X4(al0, al1, al2, al3,
                        smem_u32(&Al[(warp_m * 64 + mf * 16 + a_r) * 40 + ks * 16 + a_c]));
#pragma unroll
                for (int nf = 0; nf < 4; nf++) {
                    MMA_BF16(acc[mf][nf][0], acc[mf][nf][1], acc[mf][nf][2], acc[mf][nf][3],
                             ah0, ah1, ah2, ah3, bh0[nf], bh1[nf]);
                    MMA_BF16(acc[mf][nf][0], acc[mf][nf][1], acc[mf][nf][2], acc[mf][nf][3],
                             ah0, ah1, ah2, ah3, bl0[nf], bl1[nf]);
                    MMA_BF16(acc[mf][nf][0], acc[mf][nf][1], acc[mf][nf][2], acc[mf][nf][3],
                             al0, al1, al2, al3, bh0[nf], bh1[nf]);
                }
            }
        }
        __syncthreads();
    }

    const int gg = lane >> 2;
    const int t2 = (lane & 3) * 2;
#pragma unroll
    for (int mf = 0; mf < 4; mf++) {
#pragma unroll
        for (int nf = 0; nf < 4; nf++) {
#pragma unroll
            for (int e = 0; e < 4; e++) {
                const int row = warp_m * 64 + mf * 16 + gg + ((e >= 2) ? 8 : 0);
                const int col = warp_n * 32 + nf * 8 + t2 + (e & 1);
                const int m = m0 + row;
                const int ecol = n0 + col;
                const float v = acc[mf][nf][e];
                if (MODE == 1) {
                    const int bb = m >> 11;
                    const int ss = m & 2047;
                    const int c3 = ecol >> 10;
                    const int rem = ecol & 1023;
                    const int hh = rem >> 6;
                    const int dd = rem & 63;
                    const size_t di = (size_t)(((bb << 4) + hh) * S_ + ss) * DH_ + dd;
                    if (c3 == 0) {
                        g_q[di] = v;
                    } else if (c3 == 1) {
                        g_k[di] = v;
                    } else {
                        __half hv = __float2half_rn(v);
                        g_vh[di] = hv;
                        g_vl[di] = __float2half_rn(v - __half2float(hv));
                    }
                } else {
                    C[(size_t)m * N + ecol] = v;
                }
            }
        }
    }
}

// ---------------------------------------------------------------------------
// RoPE: reads fp32 g_q/g_k, rotates, writes split-bf16 (q scaled by QSCALE).
// ---------------------------------------------------------------------------
__global__ void rope2_kernel() {
    const int total = B_ * H_ * S_ * 32;
    int idx = blockIdx.x * blockDim.x + threadIdx.x;
    bool isq = true;
    if (idx >= total) {
        isq = false;
        idx -= total;
    }
    const float* src;
    if (isq) {
        src = &g_q[0];
    } else {
        src = &g_k[0];
    }

    const int i = idx & 31;
    const int s = (idx >> 5) & (S_ - 1);
    const int base = (idx >> 5) << 6;

    const float invf = (float)exp(-log(10000.0) * (double)i / 32.0);
    const float ang = (float)s * invf;
    const float cv = cosf(ang);
    const float sv = sinf(ang);

    const float u1 = src[base + i];
    const float u2 = src[base + 32 + i];
    float v1 = u1 * cv - u2 * sv;
    float v2 = u2 * cv + u1 * sv;
    if (isq) {
        v1 *= QSCALE;
        v2 *= QSCALE;
        __nv_bfloat16 h1 = __float2bfloat16(v1);
        __nv_bfloat16 h2 = __float2bfloat16(v2);
        g_qh[base + i] = h1;
        g_ql[base + i] = __float2bfloat16(v1 - __bfloat162float(h1));
        g_qh[base + 32 + i] = h2;
        g_ql[base + 32 + i] = __float2bfloat16(v2 - __bfloat162float(h2));
    } else {
        __nv_bfloat16 h1 = __float2bfloat16(v1);
        __nv_bfloat16 h2 = __float2bfloat16(v2);
        g_kh[base + i] = h1;
        g_kl[base + i] = __float2bfloat16(v1 - __bfloat162float(h1));
        g_kh[base + 32 + i] = h2;
        g_kl[base + 32 + i] = __float2bfloat16(v2 - __bfloat162float(h2));
    }
}

// ---------------------------------------------------------------------------
// Attention: 128 q-rows per CTA, 8 warps (16 rows each), online softmax,
// 2-stage cp.async K/V pipeline with ONE-ahead prefetch (round-10 pattern).
// ---------------------------------------------------------------------------
#define ATT_TILE 4608                        // 64*72 elems
#define ATT_STAGE_BYTES (4 * ATT_TILE * 2)   // Kh,Kl,Vh,Vl = 36864 B
#define ATTN_SMEM_BYTES (2 * ATT_STAGE_BYTES)  // 73728

__device__ __forceinline__ void attn_stage_load(char* sb, size_t base, int kt, int tid) {
    __nv_bfloat16* Kh = (__nv_bfloat16*)sb;
    __nv_bfloat16* Kl = Kh + ATT_TILE;
    __half* Vh = (__half*)(Kl + ATT_TILE);
    __half* Vl = Vh + ATT_TILE;
    for (int i = tid; i < 512; i += 256) {
        int rr = i >> 3;
        int cc = (i & 7) * 8;
        size_t gi = base + (size_t)(kt * 64 + rr) * 64 + cc;
        CP_A16(smem_u32(&Kh[rr * 72 + cc]), &g_kh[gi]);
        CP_A16(smem_u32(&Kl[rr * 72 + cc]), &g_kl[gi]);
        CP_A16(smem_u32(&Vh[rr * 72 + cc]), &g_vh[gi]);
        CP_A16(smem_u32(&Vl[rr * 72 + cc]), &g_vl[gi]);
    }
}

__global__ __launch_bounds__(256) void attn_tc() {
    extern __shared__ __align__(16) char dynsmem[];

    const int tid = threadIdx.x;
    const int lane = tid & 31;
    const int wid = tid >> 5;                          // 0..7
    const int qt2 = (int)gridDim.x - 1 - (int)blockIdx.x;  // 0..15, reversed
    const int bh = blockIdx.y;

    const size_t base = (size_t)bh * S_ * DH_;
    const int qrow0 = qt2 * 128;                       // first q row of CTA

    // stage Q (128x64 hi/lo) into stage-0 area, move to registers
    {
        __nv_bfloat16* Qh = (__nv_bfloat16*)dynsmem;       // 128*72 elems
        __nv_bfloat16* Ql = Qh + 128 * 72;
        for (int i = tid; i < 1024; i += 256) {
            int rr = i >> 3;
            int cc = (i & 7) * 8;
            *(uint4*)(&Qh[rr * 72 + cc]) =
                *(const uint4*)(&g_qh[base + (size_t)(qrow0 + rr) * 64 + cc]);
            *(uint4*)(&Ql[rr * 72 + cc]) =
                *(const uint4*)(&g_ql[base + (size_t)(qrow0 + rr) * 64 + cc]);
        }
    }
    __syncthreads();

    const int a_r = lane & 15;
    const int a_c = ((lane & 16) != 0) ? 8 : 0;
    unsigned int qh[4][4];
    unsigned int ql[4][4];
    {
        __nv_bfloat16* Qh = (__nv_bfloat16*)dynsmem;
        __nv_bfloat16* Ql = Qh + 128 * 72;
#pragma unroll
        for (int kc = 0; kc < 4; kc++) {
            LDSM_X4(qh[kc][0], qh[kc][1], qh[kc][2], qh[kc][3],
                    smem_u32(&Qh[(wid * 16 + a_r) * 72 + kc * 16 + a_c]));
            LDSM_X4(ql[kc][0], ql[kc][1], ql[kc][2], ql[kc][3],
                    smem_u32(&Ql[(wid * 16 + a_r) * 72 + kc * 16 + a_c]));
        }
    }
    __syncthreads();   // Q consumed before stage-0 overwrite

    float o[8][4];
#pragma unroll
    for (int nf = 0; nf < 8; nf++) {
#pragma unroll
        for (int e = 0; e < 4; e++) {
            o[nf][e] = 0.f;
        }
    }
    float m0r = -1e30f;
    float m1r = -1e30f;
    float l0r = 0.f;
    float l1r = 0.f;

    const int b_row = lane & 7;
    const int b_sel = ((lane >> 3) & 1) * 8;
    const int wrow_min = qrow0 + wid * 16;      // warp's first q row
    const int wrow_max = wrow_min + 15;         // warp's last q row
    const int NT = 2 * qt2 + 2;                 // 64-row k-tiles

    // prologue: stage 0 only (one-ahead prefetch discipline)
    attn_stage_load(dynsmem, base, 0, tid);
    CP_COMMIT();

    for (int kt = 0; kt < NT; kt++) {
        if (kt + 1 < NT) {
            attn_stage_load(dynsmem + ((kt + 1) & 1) * ATT_STAGE_BYTES, base, kt + 1, tid);
            CP_COMMIT();
            CP_WAIT1();
        } else {
            CP_WAIT0();
        }
        __syncthreads();

        // skip fully-masked tiles for this warp (uniform across the warp)
        if (kt * 64 <= wrow_max) {
            char* sb = dynsmem + (kt & 1) * ATT_STAGE_BYTES;
            __nv_bfloat16* Kh = (__nv_bfloat16*)sb;
            __nv_bfloat16* Kl = Kh + ATT_TILE;
            __half* Vh = (__half*)(Kl + ATT_TILE);
            __half* Vl = Vh + ATT_TILE;

            float sc[8][4];
#pragma unroll
            for (int nf = 0; nf < 8; nf++) {
#pragma unroll
                for (int e = 0; e < 4; e++) {
                    sc[nf][e] = 0.f;
                }
            }
#pragma unroll
            for (int nf = 0; nf < 8; nf++) {
#pragma unroll
                for (int kc = 0; kc < 4; kc++) {
                    unsigned int kbh0;
                    unsigned int kbh1;
                    unsigned int kbl0;
                    unsigned int kbl1;
                    LDSM_X2(kbh0, kbh1, smem_u32(&Kh[(nf * 8 + b_row) * 72 + kc * 16 + b_sel]));
                    LDSM_X2(kbl0, kbl1, smem_u32(&Kl[(nf * 8 + b_row) * 72 + kc * 16 + b_sel]));
                    MMA_BF16(sc[nf][0], sc[nf][1], sc[nf][2], sc[nf][3],
                             qh[kc][0], qh[kc][1], qh[kc][2], qh[kc][3], kbh0, kbh1);
                    MMA_BF16(sc[nf][0], sc[nf][1], sc[nf][2], sc[nf][3],
                             qh[kc][0], qh[kc][1], qh[kc][2], qh[kc][3], kbl0, kbl1);
                    MMA_BF16(sc[nf][0], sc[nf][1], sc[nf][2], sc[nf][3],
                             ql[kc][0], ql[kc][1], ql[kc][2], ql[kc][3], kbh0, kbh1);
                }
            }

            // causal mask if the tile overlaps the diagonal for this warp
            if (kt * 64 + 63 > wrow_min) {
                const int lr0 = wrow_min + (lane >> 2);
#pragma unroll
                for (int nf = 0; nf < 8; nf++) {
#pragma unroll
                    for (int e = 0; e < 4; e++) {
                        const int lr = lr0 + ((e >= 2) ? 8 : 0);
                        const int lc = kt * 64 + nf * 8 + (lane & 3) * 2 + (e & 1);
                        if (lc > lr) {
                            sc[nf][e] = -1e30f;
                        }
                    }
                }
            }

            float tm0 = -1e30f;
            float tm1 = -1e30f;
#pragma unroll
            for (int nf = 0; nf < 8; nf++) {
                tm0 = fmaxf(tm0, fmaxf(sc[nf][0], sc[nf][1]));
                tm1 = fmaxf(tm1, fmaxf(sc[nf][2], sc[nf][3]));
            }
            tm0 = fmaxf(tm0, __shfl_xor_sync(0xffffffffu, tm0, 1));
            tm0 = fmaxf(tm0, __shfl_xor_sync(0xffffffffu, tm0, 2));
            tm1 = fmaxf(tm1, __shfl_xor_sync(0xffffffffu, tm1, 1));
            tm1 = fmaxf(tm1, __shfl_xor_sync(0xffffffffu, tm1, 2));

            const float mn0 = fmaxf(m0r, tm0);
            const float mn1 = fmaxf(m1r, tm1);
            const float cr0 = exp2f(m0r - mn0);
            const float cr1 = exp2f(m1r - mn1);
            m0r = mn0;
            m1r = mn1;

            unsigned int pf[4][4];
            float ts0 = 0.f;
            float ts1 = 0.f;
#pragma unroll
            for (int kc = 0; kc < 4; kc++) {
                EX2F16X2(pf[kc][0], sc[2 * kc][0] - mn0, sc[2 * kc][1] - mn0);
                EX2F16X2(pf[kc][1], sc[2 * kc][2] - mn1, sc[2 * kc][3] - mn1);
                EX2F16X2(pf[kc][2], sc[2 * kc + 1][0] - mn0, sc[2 * kc + 1][1] - mn0);
                EX2F16X2(pf[kc][3], sc[2 * kc + 1][2] - mn1, sc[2 * kc + 1][3] - mn1);
#pragma unroll
                for (int e = 0; e < 4; e++) {
                    unsigned int u = pf[kc][e];
                    __half2 hv = *(__half2*)(&u);
                    float2 fv = __half22float2(hv);
                    if ((e & 1) == 0) {
                        ts0 += fv.x + fv.y;
                    } else {
                        ts1 += fv.x + fv.y;
                    }
                }
            }
            ts0 += __shfl_xor_sync(0xffffffffu, ts0, 1);
            ts0 += __shfl_xor_sync(0xffffffffu, ts0, 2);
            ts1 += __shfl_xor_sync(0xffffffffu, ts1, 1);
            ts1 += __shfl_xor_sync(0xffffffffu, ts1, 2);
            l0r = l0r * cr0 + ts0;
            l1r = l1r * cr1 + ts1;

#pragma unroll
            for (int nf = 0; nf < 8; nf++) {
                o[nf][0] *= cr0;
                o[nf][1] *= cr0;
                o[nf][2] *= cr1;
                o[nf][3] *= cr1;
            }

#pragma unroll
            for (int nf = 0; nf < 8; nf++) {
#pragma unroll
                for (int kc = 0; kc < 4; kc++) {
                    unsigned int vb0;
                    unsigned int vb1;
                    unsigned int wb0;
                    unsigned int wb1;
                    LDSM_X2T(vb0, vb1, smem_u32(&Vh[(kc * 16 + a_r) * 72 + nf * 8]));
                    LDSM_X2T(wb0, wb1, smem_u32(&Vl[(kc * 16 + a_r) * 72 + nf * 8]));
                    MMA_F16(o[nf][0], o[nf][1], o[nf][2], o[nf][3],
                            pf[kc][0], pf[kc][1], pf[kc][2], pf[kc][3], vb0, vb1);
                    MMA_F16(o[nf][0], o[nf][1], o[nf][2], o[nf][3],
                            pf[kc][0], pf[kc][1], pf[kc][2], pf[kc][3], wb0, wb1);
                }
            }
        }
        __syncthreads();
    }

    const float inv0 = 1.f / l0r;
    const float inv1 = 1.f / l1r;
    const int bb = bh >> 4;
    const int hh = bh & 15;
    const int row0 = wrow_min + (lane >> 2);
    const int col0 = (lane & 3) * 2;
#pragma unroll
    for (int nf = 0; nf < 8; nf++) {
        const float z00 = o[nf][0] * inv0;
        const float z01 = o[nf][1] * inv0;
        const float z10 = o[nf][2] * inv1;
        const float z11 = o[nf][3] * inv1;
        const size_t i0 = (size_t)(bb * S_ + row0) * D_ + hh * 64 + nf * 8 + col0;
        const size_t i1 = (size_t)(bb * S_ + row0 + 8) * D_ + hh * 64 + nf * 8 + col0;
        __nv_bfloat16 h00 = __float2bfloat16(z00);
        __nv_bfloat16 h01 = __float2bfloat16(z01);
        __nv_bfloat16 h10 = __float2bfloat16(z10);
        __nv_bfloat16 h11 = __float2bfloat16(z11);
        g_zhi[i0] = h00;
        g_zhi[i0 + 1] = h01;
        g_zhi[i1] = h10;
        g_zhi[i1 + 1] = h11;
        g_zlo[i0] = __float2bfloat16(z00 - __bfloat162float(h00));
        g_zlo[i0 + 1] = __float2bfloat16(z01 - __bfloat162float(h01));
        g_zlo[i1] = __float2bfloat16(z10 - __bfloat162float(h10));
        g_zlo[i1 + 1] = __float2bfloat16(z11 - __bfloat162float(h11));
    }
}

// ---------------------------------------------------------------------------
extern "C" void kernel_launch(void* const* d_in, const int* in_sizes, int n_in,
                              void* d_out, int out_size) {
    const float* x = 0;
    const float* W_qkv = 0;
    const float* W_o = 0;

    bool elem_mode = false;
    bool byte_mode = false;
    for (int i = 0; i < n_in; i++) {
        if (in_sizes[i] == 3145728)  elem_mode = true;
        if (in_sizes[i] == 12582912) byte_mode = true;
    }
    if (elem_mode) {
        for (int i = 0; i < n_in; i++) {
            if (in_sizes[i] == 4194304)      x     = (const float*)d_in[i];
            else if (in_sizes[i] == 3145728) W_qkv = (const float*)d_in[i];
            else if (in_sizes[i] == 1048576) W_o   = (const float*)d_in[i];
        }
    } else if (byte_mode) {
        for (int i = 0; i < n_in; i++) {
            if (in_sizes[i] == 16777216)      x     = (const float*)d_in[i];
            else if (in_sizes[i] == 12582912) W_qkv = (const float*)d_in[i];
            else if (in_sizes[i] == 4194304)  W_o   = (const float*)d_in[i];
        }
    }
    if (x == 0 || W_qkv == 0 || W_o == 0) {
        x     = (const float*)d_in[0];
        W_qkv = (const float*)d_in[1];
        W_o   = (const float*)d_in[2];
    }
    float* out = (float*)d_out;

    cudaFuncSetAttribute(mma_gemm<3072, 1>,
                         cudaFuncAttributeMaxDynamicSharedMemorySize, GEMM_SMEM_BYTES);
    cudaFuncSetAttribute(mma_gemm<1024, 0>,
                         cudaFuncAttributeMaxDynamicSharedMemorySize, GEMM_SMEM_BYTES);
    cudaFuncSetAttribute(attn_tc,
                         cudaFuncAttributeMaxDynamicSharedMemorySize, ATTN_SMEM_BYTES);

    // 0) split inputs to bf16 hi/lo
    split_kernel<0><<<(M_ROWS * D_ + 255) / 256, 256>>>(x, M_ROWS * D_);
    split_kernel<1><<<(D_ * 3 * D_ + 255) / 256, 256>>>(W_qkv, D_ * 3 * D_);
    split_kernel<2><<<(D_ * D_ + 255) / 256, 256>>>(W_o, D_ * D_);

    // 1) QKV projection (2-stage pipelined tensor cores)
    mma_gemm<3072, 1><<<dim3(3072 / 128, M_ROWS / 128), 256, GEMM_SMEM_BYTES>>>(0);

    // 2) RoPE + split/scale q,k
    rope2_kernel<<<(2 * B_ * H_ * S_ * 32) / 256, 256>>>();

    // 3) Online-softmax tensor-core causal flash attention, 128 q-rows/CTA
    attn_tc<<<dim3(S_ / 128, B_ * H_), 256, ATTN_SMEM_BYTES>>>();

    // 4) O-projection (2-stage pipelined tensor cores)
    mma_gemm<1024, 0><<<dim3(1024 / 128, M_ROWS / 128), 256, GEMM_SMEM_BYTES>>>(out);
}